// round 3
// baseline (speedup 1.0000x reference)
#include <cuda_runtime.h>
#include <math.h>

#define NN 100000
#define NE 1600000
#define NC 2000
#define BN_EPS 1e-5f
#define NBLKA 2048
#define NBLKC 1024
#define NBLKP 1024

typedef unsigned long long ull;

static_assert(NE % 8 == 0, "");
static_assert(NN % 4 == 0, "");

// ---------------- static scratch ----------------
__device__ __align__(16) float g_x[NN * 64];          // node features
__device__ __align__(16) float g_P[NN * 256];         // [P1 | P2] per node
__device__ __align__(16) float g_Z[(size_t)NE * 128]; // edge pre-BN activations
__device__ __align__(16) float g_nmean[NN * 64];      // seg-mean of messages
__device__ __align__(16) float g_cmean[NC * 64];
__device__ int g_deg[NN];
__device__ int g_start[NN + 1];
__device__ int g_cursor[NN];
__device__ int g_perm[NE];
__device__ int g_ccnt[NC];
__device__ int g_cstart[NC + 1];
__device__ float g_epart[NBLKA * 128 * 2];   // per-block (sum, sumsq) per edge-BN column
__device__ float g_npart[NBLKC * 128];       // per-block [sum(64) | sumsq(64)] node-BN
__device__ __align__(16) float g_eaff[256];  // a1[128], b1[128]
__device__ __align__(16) float g_naff[128];  // a2[64],  b2[64]

// ---------------- packed f32x2 helpers (Blackwell) ----------------
__device__ __forceinline__ ull pack2(float lo, float hi) {
    ull d; asm("mov.b64 %0, {%1, %2};" : "=l"(d) : "f"(lo), "f"(hi)); return d;
}
__device__ __forceinline__ float2 unpack2(ull v) {
    float2 r; asm("mov.b64 {%0, %1}, %2;" : "=f"(r.x), "=f"(r.y) : "l"(v)); return r;
}
__device__ __forceinline__ ull fma2(ull a, ull b, ull c) {
    ull d; asm("fma.rn.f32x2 %0, %1, %2, %3;" : "=l"(d) : "l"(a), "l"(b), "l"(c)); return d;
}
__device__ __forceinline__ ull add2(ull a, ull b) {
    ull d; asm("add.rn.f32x2 %0, %1, %2;" : "=l"(d) : "l"(a), "l"(b)); return d;
}

__device__ __forceinline__ float d_softplus(float x) {
    return fmaxf(x, 0.f) + __logf(1.f + __expf(-fabsf(x)));
}
__device__ __forceinline__ float d_sigmoid(float x) {
    return 1.f / (1.f + __expf(-x));
}

// ---------------- setup kernels ----------------
__global__ void k_embed(const int* __restrict__ nf, const float* __restrict__ emb) {
    int i = blockIdx.x * blockDim.x + threadIdx.x;  // over NN*16 float4s
    if (i >= NN * 16) return;
    int n = i >> 4, q = i & 15;
    ((float4*)g_x)[i] = ((const float4*)emb)[nf[n] * 16 + q];
}

__global__ void k_hist(const int* __restrict__ idx, int* __restrict__ cnt, int n) {
    int i = blockIdx.x * blockDim.x + threadIdx.x;
    if (i < n) atomicAdd(&cnt[idx[i]], 1);
}

// single-block exclusive scan, out[0..n] (out[n] = total)
__global__ void k_scan(const int* __restrict__ cnt, int* __restrict__ out, int n) {
    __shared__ int sh[1024];
    __shared__ int carry;
    if (threadIdx.x == 0) carry = 0;
    __syncthreads();
    for (int base = 0; base < n; base += 1024) {
        int i = base + threadIdx.x;
        int v = (i < n) ? cnt[i] : 0;
        sh[threadIdx.x] = v;
        __syncthreads();
        for (int off = 1; off < 1024; off <<= 1) {
            int t = (threadIdx.x >= off) ? sh[threadIdx.x - off] : 0;
            __syncthreads();
            sh[threadIdx.x] += t;
            __syncthreads();
        }
        if (i < n) out[i] = carry + sh[threadIdx.x] - v;
        __syncthreads();
        if (threadIdx.x == 0) carry += sh[1023];
        __syncthreads();
    }
    if (threadIdx.x == 0) out[n] = carry;
}

__global__ void k_fill_perm(const int* __restrict__ idx1) {
    int e = blockIdx.x * blockDim.x + threadIdx.x;
    if (e >= NE) return;
    int n = idx1[e];
    int p = atomicAdd(&g_cursor[n], 1);
    g_perm[g_start[n] + p] = e;
}

// deterministic order within each node's edge list
__global__ void k_sort_perm() {
    int n = blockIdx.x * blockDim.x + threadIdx.x;
    if (n >= NN) return;
    int s = g_start[n], e = g_start[n + 1];
    for (int i = s + 1; i < e; i++) {
        int v = g_perm[i];
        int j = i - 1;
        while (j >= s && g_perm[j] > v) { g_perm[j + 1] = g_perm[j]; j--; }
        g_perm[j + 1] = v;
    }
}

// ---------------- per-layer kernels ----------------
// P[n][0:128] = x[n] @ Wf_l[0:64,:], P[n][128:256] = x[n] @ Wf_l[64:128,:]
__global__ void __launch_bounds__(256) k_nodeP(const float* __restrict__ Wl) {
    const int t = threadIdx.x;
    const int col = t & 127;
    const int half = t >> 7;  // 0 -> P1, 1 -> P2
    float W[64];
#pragma unroll
    for (int k = 0; k < 64; k++) W[k] = Wl[(half * 64 + k) * 128 + col];
    __shared__ float sx[4 * 64];
    const int ngrp = NN / 4;
    for (int g = blockIdx.x; g < ngrp; g += NBLKP) {
        const int n0 = g * 4;
        __syncthreads();
        sx[t] = g_x[n0 * 64 + t];
        __syncthreads();
#pragma unroll
        for (int nn = 0; nn < 4; nn++) {
            float acc = 0.f;
#pragma unroll
            for (int k = 0; k < 64; k++) acc = fmaf(sx[nn * 64 + k], W[k], acc);
            g_P[(n0 + nn) * 256 + half * 128 + col] = acc;
        }
    }
}

// z[e] = P1[idx1[e]] + P2[idx2[e]] + edge_fea[e] @ W3 + bf  ; accumulate BN stats
__global__ void __launch_bounds__(64) k_edgeA(const float* __restrict__ ef,
                                              const int* __restrict__ idx1,
                                              const int* __restrict__ idx2,
                                              const float* __restrict__ Wl,
                                              const float* __restrict__ bfl) {
    const int t = threadIdx.x;  // owns columns 2t, 2t+1
    ull W[41];
#pragma unroll
    for (int k = 0; k < 41; k++) W[k] = *(const ull*)(Wl + (128 + k) * 128 + 2 * t);
    const ull bias = *(const ull*)(bfl + 2 * t);
    __shared__ ull sef[8 * 41];
    __shared__ int sidx[16];
    float s0 = 0.f, q0 = 0.f, s1 = 0.f, q1 = 0.f;
    const ull* Pv = (const ull*)g_P;
    ull* Zv = (ull*)g_Z;
    const int nch = NE / 8;
    for (int ch = blockIdx.x; ch < nch; ch += NBLKA) {
        const int e0 = ch * 8;
        __syncthreads();
        for (int i = t; i < 8 * 41; i += 64) {
            float v = ef[e0 * 41 + i];
            sef[i] = pack2(v, v);
        }
        if (t < 8) sidx[t] = idx1[e0 + t];
        else if (t < 16) sidx[t] = idx2[e0 + t - 8];
        __syncthreads();
#pragma unroll
        for (int ee = 0; ee < 8; ee++) {
            const int i1 = sidx[ee], i2 = sidx[8 + ee];
            ull acc = add2(add2(Pv[i1 * 128 + t], Pv[i2 * 128 + 64 + t]), bias);
#pragma unroll
            for (int k = 0; k < 41; k++) acc = fma2(sef[ee * 41 + k], W[k], acc);
            Zv[(size_t)(e0 + ee) * 64 + t] = acc;
            float2 a = unpack2(acc);
            s0 += a.x; q0 = fmaf(a.x, a.x, q0);
            s1 += a.y; q1 = fmaf(a.y, a.y, q1);
        }
    }
    const int c0 = 2 * t;
    g_epart[(blockIdx.x * 128 + c0) * 2 + 0] = s0;
    g_epart[(blockIdx.x * 128 + c0) * 2 + 1] = q0;
    g_epart[(blockIdx.x * 128 + c0 + 1) * 2 + 0] = s1;
    g_epart[(blockIdx.x * 128 + c0 + 1) * 2 + 1] = q1;
}

// reduce edge-BN partials -> affine a1,b1
__global__ void __launch_bounds__(1024) k_fin_edge(const float* __restrict__ g1l,
                                                   const float* __restrict__ be1l) {
    __shared__ double ss[1024], sq[1024];
    const int c = threadIdx.x & 127;
    const int sl = threadIdx.x >> 7;  // 8 slices x 256 blocks
    double s = 0.0, q = 0.0;
    for (int b = sl * 256; b < (sl + 1) * 256; b++) {
        s += (double)g_epart[(b * 128 + c) * 2 + 0];
        q += (double)g_epart[(b * 128 + c) * 2 + 1];
    }
    ss[threadIdx.x] = s; sq[threadIdx.x] = q;
    __syncthreads();
    if (threadIdx.x < 128) {
        double S = 0.0, Q = 0.0;
        for (int w = 0; w < 8; w++) { S += ss[w * 128 + threadIdx.x]; Q += sq[w * 128 + threadIdx.x]; }
        double mean = S / (double)NE;
        double var = Q / (double)NE - mean * mean;
        float a = g1l[threadIdx.x] * rsqrtf((float)var + BN_EPS);
        g_eaff[threadIdx.x] = a;
        g_eaff[128 + threadIdx.x] = be1l[threadIdx.x] - (float)mean * a;
    }
}

// per-node gather-reduce: msg = sigmoid(gate_bn)*softplus(conv_bn), seg-mean; node-BN stats
__global__ void __launch_bounds__(256) k_edgeB() {
    const int lane = threadIdx.x & 31;
    const int warp = threadIdx.x >> 5;  // 8 warps, one node each per iteration
    const float ag0 = g_eaff[lane],        bg0 = g_eaff[128 + lane];
    const float ag1 = g_eaff[32 + lane],   bg1 = g_eaff[160 + lane];
    const float ac0 = g_eaff[64 + lane],   bc0 = g_eaff[192 + lane];
    const float ac1 = g_eaff[96 + lane],   bc1 = g_eaff[224 + lane];
    float s0 = 0.f, s1 = 0.f, q0 = 0.f, q1 = 0.f;
    __shared__ float sh2[8 * 128];
    for (int n = blockIdx.x * 8 + warp; n < NN; n += NBLKC * 8) {
        const int e0 = g_start[n], e1 = g_start[n + 1];
        float acc0 = 0.f, acc1 = 0.f;
        for (int p = e0; p < e1; p++) {
            const int e = g_perm[p];
            const float* z = g_Z + (size_t)e * 128;
            float gate0 = fmaf(z[lane],      ag0, bg0);
            float gate1 = fmaf(z[32 + lane], ag1, bg1);
            float conv0 = fmaf(z[64 + lane], ac0, bc0);
            float conv1 = fmaf(z[96 + lane], ac1, bc1);
            acc0 = fmaf(d_sigmoid(gate0), d_softplus(conv0), acc0);
            acc1 = fmaf(d_sigmoid(gate1), d_softplus(conv1), acc1);
        }
        float inv = 1.f / (float)max(e1 - e0, 1);
        float m0 = acc0 * inv, m1 = acc1 * inv;
        g_nmean[n * 64 + lane] = m0;
        g_nmean[n * 64 + 32 + lane] = m1;
        s0 += m0; q0 = fmaf(m0, m0, q0);
        s1 += m1; q1 = fmaf(m1, m1, q1);
    }
    sh2[warp * 128 + lane]      = s0;
    sh2[warp * 128 + 32 + lane] = s1;
    sh2[warp * 128 + 64 + lane] = q0;
    sh2[warp * 128 + 96 + lane] = q1;
    __syncthreads();
    if (threadIdx.x < 128) {
        float v = 0.f;
        for (int w = 0; w < 8; w++) v += sh2[w * 128 + threadIdx.x];
        g_npart[blockIdx.x * 128 + threadIdx.x] = v;
    }
}

__global__ void __launch_bounds__(1024) k_fin_node(const float* __restrict__ g2l,
                                                   const float* __restrict__ be2l) {
    __shared__ double ss[1024], sq[1024];
    const int c = threadIdx.x & 63;
    const int sl = threadIdx.x >> 6;  // 16 slices x 64 blocks
    double s = 0.0, q = 0.0;
    for (int b = sl * 64; b < (sl + 1) * 64; b++) {
        s += (double)g_npart[b * 128 + c];
        q += (double)g_npart[b * 128 + 64 + c];
    }
    ss[threadIdx.x] = s; sq[threadIdx.x] = q;
    __syncthreads();
    if (threadIdx.x < 64) {
        double S = 0.0, Q = 0.0;
        for (int w = 0; w < 16; w++) { S += ss[w * 64 + threadIdx.x]; Q += sq[w * 64 + threadIdx.x]; }
        double mean = S / (double)NN;
        double var = Q / (double)NN - mean * mean;
        float a = g2l[threadIdx.x] * rsqrtf((float)var + BN_EPS);
        g_naff[threadIdx.x] = a;
        g_naff[64 + threadIdx.x] = be2l[threadIdx.x] - (float)mean * a;
    }
}

__global__ void k_update_x() {
    int i = blockIdx.x * blockDim.x + threadIdx.x;
    if (i >= NN * 64) return;
    int c = i & 63;
    float v = g_x[i] + fmaf(g_nmean[i], g_naff[c], g_naff[64 + c]);
    g_x[i] = d_softplus(v);
}

// ---------------- head ----------------
__global__ void __launch_bounds__(64) k_crysmean() {
    const int c = blockIdx.x;       // crystal
    const int col = threadIdx.x;    // 0..63
    const int s = g_cstart[c], e = g_cstart[c + 1];
    float acc = 0.f;
    for (int n = s; n < e; n++) acc += g_x[n * 64 + col];
    g_cmean[c * 64 + col] = acc / (float)max(e - s, 1);
}

__global__ void __launch_bounds__(128) k_head(const float* __restrict__ Wc,
                                              const float* __restrict__ bc,
                                              const float* __restrict__ Wo,
                                              const float* __restrict__ bo,
                                              float* __restrict__ out) {
    const int c = blockIdx.x;
    const int t = threadIdx.x;  // 0..127
    __shared__ float cm[64];
    __shared__ float r0[128], r1[128];
    if (t < 64) cm[t] = g_cmean[c * 64 + t];
    __syncthreads();
    float h = bc[t];
#pragma unroll
    for (int k = 0; k < 64; k++) h = fmaf(cm[k], Wc[k * 128 + t], h);
    h = d_softplus(h);
    r0[t] = h * Wo[t * 2 + 0];
    r1[t] = h * Wo[t * 2 + 1];
    __syncthreads();
    for (int off = 64; off > 0; off >>= 1) {
        if (t < off) { r0[t] += r0[t + off]; r1[t] += r1[t + off]; }
        __syncthreads();
    }
    if (t == 0) {
        out[c * 2 + 0] = r0[0] + bo[0];
        out[c * 2 + 1] = r1[0] + bo[1];
    }
}

// ---------------- launch ----------------
extern "C" void kernel_launch(void* const* d_in, const int* in_sizes, int n_in,
                              void* d_out, int out_size) {
    const int*   nf   = (const int*)d_in[0];
    const float* ef   = (const float*)d_in[1];
    const int*   idx1 = (const int*)d_in[2];
    const int*   idx2 = (const int*)d_in[3];
    const int*   idx3 = (const int*)d_in[4];
    const float* emb  = (const float*)d_in[5];
    const float* Wf   = (const float*)d_in[6];
    const float* bf   = (const float*)d_in[7];
    const float* g1   = (const float*)d_in[8];
    const float* be1  = (const float*)d_in[9];
    const float* g2   = (const float*)d_in[10];
    const float* be2  = (const float*)d_in[11];
    const float* Wc   = (const float*)d_in[12];
    const float* bc   = (const float*)d_in[13];
    const float* Wo   = (const float*)d_in[14];
    const float* bo   = (const float*)d_in[15];
    float* out = (float*)d_out;

    void *p_deg, *p_cursor, *p_ccnt, *p_start, *p_cstart;
    cudaGetSymbolAddress(&p_deg, g_deg);
    cudaGetSymbolAddress(&p_cursor, g_cursor);
    cudaGetSymbolAddress(&p_ccnt, g_ccnt);
    cudaGetSymbolAddress(&p_start, g_start);
    cudaGetSymbolAddress(&p_cstart, g_cstart);

    cudaMemsetAsync(p_deg, 0, NN * sizeof(int));
    cudaMemsetAsync(p_cursor, 0, NN * sizeof(int));
    cudaMemsetAsync(p_ccnt, 0, NC * sizeof(int));

    k_embed<<<(NN * 16 + 255) / 256, 256>>>(nf, emb);
    k_hist<<<(NE + 255) / 256, 256>>>(idx1, (int*)p_deg, NE);
    k_scan<<<1, 1024>>>((const int*)p_deg, (int*)p_start, NN);
    k_fill_perm<<<(NE + 255) / 256, 256>>>(idx1);
    k_sort_perm<<<(NN + 255) / 256, 256>>>();
    k_hist<<<(NN + 255) / 256, 256>>>(idx3, (int*)p_ccnt, NN);
    k_scan<<<1, 1024>>>((const int*)p_ccnt, (int*)p_cstart, NC);

    for (int l = 0; l < 3; l++) {
        const float* Wl = Wf + (size_t)l * 169 * 128;
        k_nodeP<<<NBLKP, 256>>>(Wl);
        k_edgeA<<<NBLKA, 64>>>(ef, idx1, idx2, Wl, bf + l * 128);
        k_fin_edge<<<1, 1024>>>(g1 + l * 128, be1 + l * 128);
        k_edgeB<<<NBLKC, 256>>>();
        k_fin_node<<<1, 1024>>>(g2 + l * 64, be2 + l * 64);
        k_update_x<<<(NN * 64 + 255) / 256, 256>>>();
    }

    k_crysmean<<<NC, 64>>>();
    k_head<<<NC, 128>>>(Wc, bc, Wo, bo, out);
}